// round 11
// baseline (speedup 1.0000x reference)
#include <cuda_runtime.h>
#include <cuda_bf16.h>
#include <math.h>
#include <stdint.h>

// ---------------- problem constants ----------------
#define N_STMT 100000
#define N_FUNC 50000
#define T_TOK  16
#define VOCAB  50000
#define C_DIM  128
#define H_HEAD 8
#define D_HEAD 16
#define L_LAYER 2
#define E_EDGE 200000

// ---------------- scratch arena ----------------
#define SZ_S ((size_t)N_STMT * C_DIM)
#define SZ_F ((size_t)N_FUNC * C_DIM)
#define OFF_X0   ((size_t)0)
#define OFF_X1   (OFF_X0 + SZ_S)
#define OFF_XN0  (OFF_X1 + SZ_F)
#define OFF_XN1  (OFF_XN0 + SZ_S)
#define OFF_K0   (OFF_XN1 + SZ_F)
#define OFF_Q0   (OFF_K0 + SZ_S)
#define OFF_V0   (OFF_Q0 + SZ_S)
#define OFF_K1   (OFF_V0 + SZ_S)
#define OFF_Q1   (OFF_K1 + SZ_F)
#define OFF_V1   (OFF_Q1 + SZ_F)
#define OFF_KR   (OFF_V1 + SZ_F)
#define OFF_VR   (OFF_KR + SZ_S)
#define OFF_AGG0 (OFF_VR + SZ_S)
#define OFF_AGG1 (OFF_AGG0 + SZ_S)
#define OFF_CSR  (OFF_AGG1 + SZ_F)
#define CSR_INTS ((size_t)1100016)
// bf16 weight cache: 18 matrices x 16384 halves, hi then lo = 589824 halves = 294912 floats
#define OFF_WT   (OFF_CSR + CSR_INTS)
#define WT_FLOATS ((size_t)294912)
#define SCRATCH_TOTAL (OFF_WT + WT_FLOATS)

__device__ float g_scratch[SCRATCH_TOTAL];

#define WT_HALVES 16384
#define N_WMAT 18

// ---------------- device helpers ----------------
__device__ __forceinline__ float gelu_tanh(float x) {
    const float c = 0.7978845608028654f;
    float x3 = x * x * x;
    return 0.5f * x * (1.0f + tanhf(c * (x + 0.044715f * x3)));
}

__device__ __forceinline__ void split2(float x, float y, uint32_t& hi, uint32_t& lo) {
    __nv_bfloat16 hx = __float2bfloat16(x), hy = __float2bfloat16(y);
    __nv_bfloat16 lx = __float2bfloat16(x - __bfloat162float(hx));
    __nv_bfloat16 ly = __float2bfloat16(y - __bfloat162float(hy));
    hi = (uint32_t)__bfloat16_as_ushort(hx) | ((uint32_t)__bfloat16_as_ushort(hy) << 16);
    lo = (uint32_t)__bfloat16_as_ushort(lx) | ((uint32_t)__bfloat16_as_ushort(ly) << 16);
}

__device__ __forceinline__ void mma16816(float* c, const uint32_t* a, uint32_t b0, uint32_t b1) {
    asm volatile(
        "mma.sync.aligned.m16n8k16.row.col.f32.bf16.bf16.f32 "
        "{%0,%1,%2,%3}, {%4,%5,%6,%7}, {%8,%9}, {%0,%1,%2,%3};"
        : "+f"(c[0]), "+f"(c[1]), "+f"(c[2]), "+f"(c[3])
        : "r"(a[0]), "r"(a[1]), "r"(a[2]), "r"(a[3]), "r"(b0), "r"(b1));
}

// ---------------- fills / small utils ----------------
__global__ void fill_kernel(float* __restrict__ p, float v, int n) {
    int i = blockIdx.x * blockDim.x + threadIdx.x;
    if (i < n) p[i] = v;
}
__global__ void zero_int_kernel(int* __restrict__ p, int n) {
    int i = blockIdx.x * blockDim.x + threadIdx.x;
    if (i < n) p[i] = 0;
}
__global__ void copy_int_kernel(const int* __restrict__ a, int* __restrict__ b, int n) {
    int i = blockIdx.x * blockDim.x + threadIdx.x;
    if (i < n) b[i] = a[i];
}

// ---------------- CSR build ----------------
__global__ void count_kernel(const int* __restrict__ dst, int* __restrict__ deg, int n) {
    int i = blockIdx.x * blockDim.x + threadIdx.x;
    if (i < n) atomicAdd(&deg[dst[i]], 1);
}
__global__ void scan_kernel(const int* __restrict__ deg, int* __restrict__ rowptr, int N) {
    __shared__ int part[1024];
    int tid = threadIdx.x;
    int chunk = (N + 1023) >> 10;
    int start = tid * chunk;
    int end = min(start + chunk, N);
    int s = 0;
    for (int i = start; i < end; i++) s += deg[i];
    part[tid] = s;
    __syncthreads();
    for (int d = 1; d < 1024; d <<= 1) {
        int v = (tid >= d) ? part[tid - d] : 0;
        __syncthreads();
        part[tid] += v;
        __syncthreads();
    }
    int off = part[tid] - s;
    for (int i = start; i < end; i++) { rowptr[i] = off; off += deg[i]; }
    if (tid == 1023) rowptr[N] = part[1023];
}
__global__ void fill_csr_kernel(const int* __restrict__ dst, int* __restrict__ cursor,
                                int* __restrict__ perm, int n) {
    int i = blockIdx.x * blockDim.x + threadIdx.x;
    if (i < n) {
        int pos = atomicAdd(&cursor[dst[i]], 1);
        perm[pos] = i;
    }
}

// ---------------- embedding mean-pool + relu ----------------
__global__ void pool_kernel(const int* __restrict__ tok, const float* __restrict__ emb,
                            float* __restrict__ out, int N) {
    int n = blockIdx.x;
    int c = threadIdx.x;
    __shared__ int ts[T_TOK];
    if (c < T_TOK) ts[c] = tok[n * T_TOK + c];
    __syncthreads();
    float s = 0.0f;
#pragma unroll
    for (int t = 0; t < T_TOK; t++)
        s += emb[(size_t)ts[t] * C_DIM + c];
    s *= (1.0f / (float)T_TOK);
    out[(size_t)n * C_DIM + c] = fmaxf(s, 0.0f);
}

// ---------------- weight prep: W[k][n] fp32 -> Wt_hi/Wt_lo[n][k] bf16 ----------------
// one block per weight matrix; dynamic smem = 128*132*4 bytes
__global__ void prep_w(const float* __restrict__ lin_w, const float* __restrict__ kw,
                       const float* __restrict__ qw, const float* __restrict__ vw,
                       const float* __restrict__ aw,
                       __nv_bfloat16* __restrict__ whi, __nv_bfloat16* __restrict__ wlo) {
    extern __shared__ float st[];   // [128][132]
    int w = blockIdx.x;
    const float* src;
    if (w < 2) {
        src = lin_w + (size_t)w * WT_HALVES;
    } else {
        int grp = (w - 2) >> 2, sub = (w - 2) & 3;
        const float* b = (grp == 0) ? kw : (grp == 1) ? qw : (grp == 2) ? vw : aw;
        src = b + (size_t)sub * WT_HALVES;
    }
    int tid = threadIdx.x;
#pragma unroll
    for (int v = 0; v < 16; v++) {
        int i = tid + v * 256;
        int k = i >> 5, n4 = (i & 31) << 2;
        float4 f = *(const float4*)&src[(size_t)k * C_DIM + n4];
        *(float4*)&st[k * 132 + n4] = f;
    }
    __syncthreads();
    __nv_bfloat16* oh = whi + (size_t)w * WT_HALVES;
    __nv_bfloat16* ol = wlo + (size_t)w * WT_HALVES;
#pragma unroll
    for (int v = 0; v < 8; v++) {
        int u = tid + v * 256;          // 0..2047
        int n = u & 127, kc = u >> 7;   // kc: 0..15 (8 k each)
        uint16_t hb[8], lb[8];
#pragma unroll
        for (int j = 0; j < 8; j++) {
            float f = st[(kc * 8 + j) * 132 + n];
            __nv_bfloat16 h = __float2bfloat16(f);
            __nv_bfloat16 l = __float2bfloat16(f - __bfloat162float(h));
            hb[j] = __bfloat16_as_ushort(h);
            lb[j] = __bfloat16_as_ushort(l);
        }
        *(uint4*)&oh[n * C_DIM + kc * 8] = *(uint4*)hb;
        *(uint4*)&ol[n * C_DIM + kc * 8] = *(uint4*)lb;
    }
}

// ---------------- mma.sync GEMM: Y[N,128] = epi( act(X) @ W + b ) ----------------
// 256 threads = 8 warps (4 m-tiles x 2 n-halves); warp tile 32x64.
// B (=W^T, [n][k]) staged in smem from the bf16 cache; A loaded from global as float2,
// split into bf16 hi/lo in registers. D = Ahi*Bhi + Ahi*Blo + Alo*Bhi.
// EPI: 0=none, 1=relu, 2=skip-blend. dynamic smem = 2*128*136*2 bytes.
#define BROW 136
template<int IN_GELU, int EPI>
__global__ void __launch_bounds__(256, 2)
mma_gemm(const float* __restrict__ X,
         const __nv_bfloat16* __restrict__ whi, const __nv_bfloat16* __restrict__ wlo,
         const float* __restrict__ bias, float* __restrict__ Y,
         const float* __restrict__ Xold, const float* __restrict__ skipp, int N) {
    extern __shared__ char smraw[];
    __nv_bfloat16* Bh = (__nv_bfloat16*)smraw;                    // [128][BROW]
    __nv_bfloat16* Bl = (__nv_bfloat16*)(smraw + 128 * BROW * 2); // [128][BROW]

    int tid = threadIdx.x;
    int wid = tid >> 5, lane = tid & 31;
    int g = lane >> 2, tq = lane & 3;
    int row0 = blockIdx.x * 128;

    // stage B (hi & lo): 128 rows x 128 halves, 16B units
#pragma unroll
    for (int v = 0; v < 8; v++) {
        int idx = tid + v * 256;        // 0..2047
        int r = idx >> 4, c8 = (idx & 15) * 8;
        *(uint4*)&Bh[r * BROW + c8] = *(const uint4*)&whi[r * C_DIM + c8];
        *(uint4*)&Bl[r * BROW + c8] = *(const uint4*)&wlo[r * C_DIM + c8];
    }
    __syncthreads();

    int wm = wid & 3, wn = wid >> 2;
    int m0 = wm * 32, n0 = wn * 64;

    float acc[16][4];   // [mi*8+ni][4]
#pragma unroll
    for (int f = 0; f < 16; f++)
#pragma unroll
        for (int j = 0; j < 4; j++) acc[f][j] = 0.0f;

    for (int ks = 0; ks < 8; ks++) {
        int kb = ks * 16 + tq * 2;
        // ---- A fragments: load float2 from global, gelu, split hi/lo ----
        uint32_t ahi[2][4], alo[2][4];
#pragma unroll
        for (int mi = 0; mi < 2; mi++) {
            int r  = row0 + m0 + mi * 16 + g;
            int r8 = r + 8;
            float2 x0 = make_float2(0.f, 0.f), x1 = x0, x2 = x0, x3 = x0;
            if (r < N) {
                x0 = *(const float2*)&X[(size_t)r * C_DIM + kb];
                x2 = *(const float2*)&X[(size_t)r * C_DIM + kb + 8];
            }
            if (r8 < N) {
                x1 = *(const float2*)&X[(size_t)r8 * C_DIM + kb];
                x3 = *(const float2*)&X[(size_t)r8 * C_DIM + kb + 8];
            }
            if (IN_GELU) {
                x0.x = gelu_tanh(x0.x); x0.y = gelu_tanh(x0.y);
                x1.x = gelu_tanh(x1.x); x1.y = gelu_tanh(x1.y);
                x2.x = gelu_tanh(x2.x); x2.y = gelu_tanh(x2.y);
                x3.x = gelu_tanh(x3.x); x3.y = gelu_tanh(x3.y);
            }
            split2(x0.x, x0.y, ahi[mi][0], alo[mi][0]);
            split2(x1.x, x1.y, ahi[mi][1], alo[mi][1]);
            split2(x2.x, x2.y, ahi[mi][2], alo[mi][2]);
            split2(x3.x, x3.y, ahi[mi][3], alo[mi][3]);
        }
        // ---- B fragments from smem + MMAs ----
#pragma unroll
        for (int ni = 0; ni < 8; ni++) {
            int nr = n0 + ni * 8 + g;
            uint32_t bh0 = *(const uint32_t*)&Bh[nr * BROW + kb];
            uint32_t bh1 = *(const uint32_t*)&Bh[nr * BROW + kb + 8];
            uint32_t bl0 = *(const uint32_t*)&Bl[nr * BROW + kb];
            uint32_t bl1 = *(const uint32_t*)&Bl[nr * BROW + kb + 8];
#pragma unroll
            for (int mi = 0; mi < 2; mi++) {
                mma16816(acc[mi * 8 + ni], ahi[mi], bh0, bh1);
                mma16816(acc[mi * 8 + ni], ahi[mi], bl0, bl1);
                mma16816(acc[mi * 8 + ni], alo[mi], bh0, bh1);
            }
        }
    }

    // ---- epilogue ----
    float gg = 0.0f, og = 0.0f;
    if (EPI == 2) {
        gg = 1.0f / (1.0f + expf(-skipp[0]));
        og = 1.0f - gg;
    }
#pragma unroll
    for (int mi = 0; mi < 2; mi++) {
#pragma unroll
        for (int half = 0; half < 2; half++) {
            int r = row0 + m0 + mi * 16 + g + half * 8;
            if (r >= N) continue;
#pragma unroll
            for (int ni = 0; ni < 8; ni++) {
                int c = n0 + ni * 8 + tq * 2;
                float o0 = acc[mi * 8 + ni][half * 2 + 0] + bias[c];
                float o1 = acc[mi * 8 + ni][half * 2 + 1] + bias[c + 1];
                if (EPI == 1) { o0 = fmaxf(o0, 0.0f); o1 = fmaxf(o1, 0.0f); }
                if (EPI == 2) {
                    float2 xo = *(const float2*)&Xold[(size_t)r * C_DIM + c];
                    o0 = gg * o0 + og * xo.x;
                    o1 = gg * o1 + og * xo.y;
                }
                *(float2*)&Y[(size_t)r * C_DIM + c] = make_float2(o0, o1);
            }
        }
    }
}

// ---------------- fused per-head relation transforms ----------------
__global__ void rel2_kernel(const float* __restrict__ K, const float* __restrict__ V,
                            const float* __restrict__ A, const float* __restrict__ M,
                            float* __restrict__ KR, float* __restrict__ VR, int N) {
    __shared__ float As[H_HEAD * D_HEAD * D_HEAD];
    __shared__ float Ms[H_HEAD * D_HEAD * D_HEAD];
    __shared__ float kin[4][C_DIM];
    __shared__ float vin[4][C_DIM];
    int tid = threadIdx.y * C_DIM + threadIdx.x;
    for (int i = tid; i < H_HEAD * D_HEAD * D_HEAD; i += 512) {
        As[i] = A[i];
        Ms[i] = M[i];
    }
    int n = blockIdx.x * 4 + threadIdx.y;
    int c = threadIdx.x;
    int h = c >> 4, e = c & 15;
    if (n < N) {
        kin[threadIdx.y][c] = K[(size_t)n * C_DIM + c];
        vin[threadIdx.y][c] = V[(size_t)n * C_DIM + c];
    }
    __syncthreads();
    if (n < N) {
        float sk = 0.0f, sv = 0.0f;
#pragma unroll
        for (int d = 0; d < D_HEAD; d++) {
            float a = As[(h * 16 + d) * 16 + e];
            float m = Ms[(h * 16 + d) * 16 + e];
            sk = fmaf(kin[threadIdx.y][h * 16 + d], a, sk);
            sv = fmaf(vin[threadIdx.y][h * 16 + d], m, sv);
        }
        KR[(size_t)n * C_DIM + c] = sk;
        VR[(size_t)n * C_DIM + c] = sv;
    }
}

// ---------------- CSR gather: one-pass online softmax + aggregation ----------------
__global__ void gather_kernel(const int* __restrict__ rowptr, const int* __restrict__ perm,
                              const int* __restrict__ srcarr,
                              const float* __restrict__ Q, const float* __restrict__ KR,
                              const float* __restrict__ VR, const float* __restrict__ prel,
                              float* __restrict__ agg, int Ndst) {
    int idx = blockIdx.x * blockDim.x + threadIdx.x;
    if (idx >= Ndst * H_HEAD) return;
    int d = idx >> 3, h = idx & 7;
    int beg = rowptr[d], end = rowptr[d + 1];
    if (beg == end) return;
    float pscale = prel[h] * 0.25f;
    const float4* qp = (const float4*)&Q[(size_t)d * C_DIM + h * 16];
    float4 q0 = qp[0], q1 = qp[1], q2 = qp[2], q3 = qp[3];
    float m = -INFINITY, s = 0.0f;
    float acc[16];
#pragma unroll
    for (int i = 0; i < 16; i++) acc[i] = 0.0f;
    for (int j = beg; j < end; j++) {
        int sn = srcarr[perm[j]];
        const float4* kp = (const float4*)&KR[(size_t)sn * C_DIM + h * 16];
        float4 k0 = kp[0], k1 = kp[1], k2 = kp[2], k3 = kp[3];
        float l = q0.x * k0.x + q0.y * k0.y + q0.z * k0.z + q0.w * k0.w
                + q1.x * k1.x + q1.y * k1.y + q1.z * k1.z + q1.w * k1.w
                + q2.x * k2.x + q2.y * k2.y + q2.z * k2.z + q2.w * k2.w
                + q3.x * k3.x + q3.y * k3.y + q3.z * k3.z + q3.w * k3.w;
        l *= pscale;
        float mn = fmaxf(m, l);
        float sc = expf(m - mn);
        float w  = expf(l - mn);
        s = s * sc + w;
        m = mn;
        const float4* vp = (const float4*)&VR[(size_t)sn * C_DIM + h * 16];
#pragma unroll
        for (int i = 0; i < 4; i++) {
            float4 v = vp[i];
            acc[4 * i + 0] = acc[4 * i + 0] * sc + w * v.x;
            acc[4 * i + 1] = acc[4 * i + 1] * sc + w * v.y;
            acc[4 * i + 2] = acc[4 * i + 2] * sc + w * v.z;
            acc[4 * i + 3] = acc[4 * i + 3] * sc + w * v.w;
        }
    }
    float inv = 1.0f / (s + 1e-16f);
    float4* ap = (float4*)&agg[(size_t)d * C_DIM + h * 16];
#pragma unroll
    for (int i = 0; i < 4; i++) {
        float4 a = ap[i];
        a.x += acc[4 * i + 0] * inv;
        a.y += acc[4 * i + 1] * inv;
        a.z += acc[4 * i + 2] * inv;
        a.w += acc[4 * i + 3] * inv;
        ap[i] = a;
    }
}

// ---------------- host orchestration ----------------
static inline int cdiv(int a, int b) { return (a + b - 1) / b; }

#define SMEM_PREP (128 * 132 * 4)
#define SMEM_MMA  (2 * 128 * BROW * 2)

extern "C" void kernel_launch(void* const* d_in, const int* in_sizes, int n_in,
                              void* d_out, int out_size) {
    (void)in_sizes; (void)n_in; (void)out_size;
    const int*   tok_s = (const int*)d_in[0];
    const int*   tok_f = (const int*)d_in[1];
    const int*   esrc[3] = {(const int*)d_in[2], (const int*)d_in[4], (const int*)d_in[6]};
    const int*   edst[3] = {(const int*)d_in[3], (const int*)d_in[5], (const int*)d_in[7]};
    const float* emb   = (const float*)d_in[8];
    const float* lin_w = (const float*)d_in[9];
    const float* lin_b = (const float*)d_in[10];
    const float* kw = (const float*)d_in[11], *kbi = (const float*)d_in[12];
    const float* qw = (const float*)d_in[13], *qbi = (const float*)d_in[14];
    const float* vw = (const float*)d_in[15], *vbi = (const float*)d_in[16];
    const float* aw = (const float*)d_in[17], *abi = (const float*)d_in[18];
    const float* skip  = (const float*)d_in[19];
    const float* a_rel = (const float*)d_in[20];
    const float* m_rel = (const float*)d_in[21];
    const float* p_rel = (const float*)d_in[22];
    float* out = (float*)d_out;

    float* S = nullptr;
    cudaGetSymbolAddress((void**)&S, g_scratch);

    cudaFuncSetAttribute(prep_w, cudaFuncAttributeMaxDynamicSharedMemorySize, SMEM_PREP);
    cudaFuncSetAttribute(mma_gemm<0, 0>, cudaFuncAttributeMaxDynamicSharedMemorySize, SMEM_MMA);
    cudaFuncSetAttribute(mma_gemm<0, 1>, cudaFuncAttributeMaxDynamicSharedMemorySize, SMEM_MMA);
    cudaFuncSetAttribute(mma_gemm<1, 2>, cudaFuncAttributeMaxDynamicSharedMemorySize, SMEM_MMA);

    float* x[2]    = {S + OFF_X0,  S + OFF_X1};
    float* xn[2]   = {S + OFF_XN0, S + OFF_XN1};
    float* bufK[2] = {S + OFF_K0,  S + OFF_K1};
    float* bufQ[2] = {S + OFF_Q0,  S + OFF_Q1};
    float* bufV[2] = {S + OFF_V0,  S + OFF_V1};
    float* kr   = S + OFF_KR;
    float* vr   = S + OFF_VR;
    float* agg[2] = {S + OFF_AGG0, S + OFF_AGG1};
    __nv_bfloat16* whi = (__nv_bfloat16*)(S + OFF_WT);
    __nv_bfloat16* wlo = whi + (size_t)N_WMAT * WT_HALVES;

    const int NN[2] = {N_STMT, N_FUNC};
    const int ST[3] = {0, 0, 1};
    const int DT[3] = {0, 1, 0};

    // ---- weight cache: transpose + bf16 hi/lo split, once ----
    prep_w<<<N_WMAT, 256, SMEM_PREP>>>(lin_w, kw, qw, vw, aw, whi, wlo);

    // weight-cache index helpers: lin: w=t; kw: 2+(l*2+t); qw: 6+..; vw: 10+..; aw: 14+..
    auto WHI = [&](int w) { return whi + (size_t)w * WT_HALVES; };
    auto WLO = [&](int w) { return wlo + (size_t)w * WT_HALVES; };

    // ---- CSR region ----
    int* csr = (int*)(S + OFF_CSR);
    const int ndst_r[3] = {N_STMT, N_FUNC, N_STMT};
    int* rp[3]; int* pm[3]; int* cu[3];
    {
        size_t off = 0;
        for (int r = 0; r < 3; r++) {
            rp[r] = csr + off; off += (size_t)ndst_r[r] + 1;
            pm[r] = csr + off; off += E_EDGE;
            cu[r] = csr + off; off += ndst_r[r];
        }
    }
    for (int r = 0; r < 3; r++) {
        int nd = ndst_r[r];
        zero_int_kernel<<<cdiv(nd, 256), 256>>>(cu[r], nd);
        count_kernel<<<cdiv(E_EDGE, 256), 256>>>(edst[r], cu[r], E_EDGE);
        scan_kernel<<<1, 1024>>>(cu[r], rp[r], nd);
        copy_int_kernel<<<cdiv(nd, 256), 256>>>(rp[r], cu[r], nd);
        fill_csr_kernel<<<cdiv(E_EDGE, 256), 256>>>(edst[r], cu[r], pm[r], E_EDGE);
    }

    // ---- encode ----
    pool_kernel<<<N_STMT, C_DIM>>>(tok_s, emb, agg[0], N_STMT);
    pool_kernel<<<N_FUNC, C_DIM>>>(tok_f, emb, agg[1], N_FUNC);
    mma_gemm<0, 1><<<cdiv(N_STMT, 128), 256, SMEM_MMA>>>(
        agg[0], WHI(0), WLO(0), lin_b, x[0], nullptr, nullptr, N_STMT);
    mma_gemm<0, 1><<<cdiv(N_FUNC, 128), 256, SMEM_MMA>>>(
        agg[1], WHI(1), WLO(1), lin_b + C_DIM, x[1], nullptr, nullptr, N_FUNC);

    float* cur[2] = {x[0], x[1]};
    float* nxt[2] = {xn[0], xn[1]};

    for (int l = 0; l < L_LAYER; l++) {
        for (int t = 0; t < 2; t++) {
            int lt = l * 2 + t;
            size_t bo = (size_t)lt * C_DIM;
            int nb = cdiv(NN[t], 128);
            mma_gemm<0, 0><<<nb, 256, SMEM_MMA>>>(
                cur[t], WHI(2 + lt), WLO(2 + lt), kbi + bo, bufK[t], nullptr, nullptr, NN[t]);
            mma_gemm<0, 0><<<nb, 256, SMEM_MMA>>>(
                cur[t], WHI(6 + lt), WLO(6 + lt), qbi + bo, bufQ[t], nullptr, nullptr, NN[t]);
            mma_gemm<0, 0><<<nb, 256, SMEM_MMA>>>(
                cur[t], WHI(10 + lt), WLO(10 + lt), vbi + bo, bufV[t], nullptr, nullptr, NN[t]);
        }
        fill_kernel<<<cdiv((int)(SZ_S + SZ_F), 256), 256>>>(agg[0], 0.0f, (int)(SZ_S + SZ_F));

        for (int r = 0; r < 3; r++) {
            int st = ST[r], dt = DT[r];
            size_t ro = (size_t)(l * 3 + r) * H_HEAD * D_HEAD * D_HEAD;
            dim3 rb(C_DIM, 4);
            rel2_kernel<<<cdiv(NN[st], 4), rb>>>(bufK[st], bufV[st], a_rel + ro, m_rel + ro,
                                                 kr, vr, NN[st]);
            const float* pr = p_rel + (size_t)(l * 3 + r) * H_HEAD;
            gather_kernel<<<cdiv(NN[dt] * H_HEAD, 256), 256>>>(
                rp[r], pm[r], esrc[r], bufQ[dt], kr, vr, pr, agg[dt], NN[dt]);
        }

        for (int t = 0; t < 2; t++) {
            int lt = l * 2 + t;
            size_t bo = (size_t)lt * C_DIM;
            float* yo = (l == L_LAYER - 1)
                        ? out + (t == 1 ? (size_t)N_STMT * C_DIM : 0)
                        : nxt[t];
            mma_gemm<1, 2><<<cdiv(NN[t], 128), 256, SMEM_MMA>>>(
                agg[t], WHI(14 + lt), WLO(14 + lt), abi + bo, yo,
                cur[t], skip + lt, NN[t]);
        }
        float* t0 = cur[0]; float* t1 = cur[1];
        cur[0] = nxt[0]; cur[1] = nxt[1];
        nxt[0] = t0; nxt[1] = t1;
    }
}

// round 13
// speedup vs baseline: 1.5733x; 1.5733x over previous
#include <cuda_runtime.h>
#include <cuda_bf16.h>
#include <math.h>
#include <stdint.h>

// ---------------- problem constants ----------------
#define N_STMT 100000
#define N_FUNC 50000
#define T_TOK  16
#define VOCAB  50000
#define C_DIM  128
#define H_HEAD 8
#define D_HEAD 16
#define L_LAYER 2
#define E_EDGE 200000

// ---------------- scratch arena ----------------
#define SZ_S ((size_t)N_STMT * C_DIM)
#define SZ_F ((size_t)N_FUNC * C_DIM)
#define OFF_X0   ((size_t)0)
#define OFF_X1   (OFF_X0 + SZ_S)
#define OFF_XN0  (OFF_X1 + SZ_F)
#define OFF_XN1  (OFF_XN0 + SZ_S)
#define OFF_K0   (OFF_XN1 + SZ_F)
#define OFF_Q0   (OFF_K0 + SZ_S)
#define OFF_V0   (OFF_Q0 + SZ_S)
#define OFF_K1   (OFF_V0 + SZ_S)
#define OFF_Q1   (OFF_K1 + SZ_F)
#define OFF_V1   (OFF_Q1 + SZ_F)
#define OFF_KR   (OFF_V1 + SZ_F)
#define OFF_VR   (OFF_KR + SZ_S)
#define OFF_AGG0 (OFF_VR + SZ_S)
#define OFF_AGG1 (OFF_AGG0 + SZ_S)
#define OFF_CSR  (OFF_AGG1 + SZ_F)
#define CSR_INTS ((size_t)1100016)
// bf16 weight cache: 18 matrices x 16384 halves, hi then lo
#define OFF_WT   (OFF_CSR + CSR_INTS)
#define WT_FLOATS ((size_t)294912)
// bf16 split activation buffer: hi (SZ_S halves) + lo (SZ_S halves) = SZ_S floats
#define OFF_XSP  (OFF_WT + WT_FLOATS)
#define SCRATCH_TOTAL (OFF_XSP + SZ_S)

__device__ float g_scratch[SCRATCH_TOTAL];

#define WT_HALVES 16384
#define N_WMAT 18
#define BROW 136

// ---------------- device helpers ----------------
__device__ __forceinline__ float gelu_tanh(float x) {
    const float c = 0.7978845608028654f;
    float x3 = x * x * x;
    return 0.5f * x * (1.0f + tanhf(c * (x + 0.044715f * x3)));
}

__device__ __forceinline__ uint32_t smem_u32(const void* p) {
    uint32_t a;
    asm("{ .reg .u64 t; cvta.to.shared.u64 t, %1; cvt.u32.u64 %0, t; }" : "=r"(a) : "l"(p));
    return a;
}

__device__ __forceinline__ void mma16816(float* c, const uint32_t* a, uint32_t b0, uint32_t b1) {
    asm volatile(
        "mma.sync.aligned.m16n8k16.row.col.f32.bf16.bf16.f32 "
        "{%0,%1,%2,%3}, {%4,%5,%6,%7}, {%8,%9}, {%0,%1,%2,%3};"
        : "+f"(c[0]), "+f"(c[1]), "+f"(c[2]), "+f"(c[3])
        : "r"(a[0]), "r"(a[1]), "r"(a[2]), "r"(a[3]), "r"(b0), "r"(b1));
}

#define LDM4(r0, r1, r2, r3, addr) \
    asm volatile("ldmatrix.sync.aligned.m8n8.x4.shared.b16 {%0,%1,%2,%3}, [%4];" \
        : "=r"(r0), "=r"(r1), "=r"(r2), "=r"(r3) : "r"(addr))

// ---------------- fills ----------------
__global__ void fill_kernel(float* __restrict__ p, float v, int n) {
    int i = blockIdx.x * blockDim.x + threadIdx.x;
    if (i < n) p[i] = v;
}

// ---------------- merged CSR build ----------------
__global__ void zero3_kernel(int* c0, int* c1, int* c2, int n0, int n1, int n2) {
    int i = blockIdx.x * blockDim.x + threadIdx.x;
    if (i < n0) c0[i] = 0;
    else if (i < n0 + n1) c1[i - n0] = 0;
    else if (i < n0 + n1 + n2) c2[i - n0 - n1] = 0;
}
__global__ void count3_kernel(const int* d0, const int* d1, const int* d2,
                              int* c0, int* c1, int* c2) {
    int i = blockIdx.x * blockDim.x + threadIdx.x;
    if (i < E_EDGE) atomicAdd(&c0[d0[i]], 1);
    else if (i < 2 * E_EDGE) atomicAdd(&c1[d1[i - E_EDGE]], 1);
    else if (i < 3 * E_EDGE) atomicAdd(&c2[d2[i - 2 * E_EDGE]], 1);
}
// 3 blocks, one per relation
__global__ void scan3_kernel(const int* g0, const int* g1, const int* g2,
                             int* r0, int* r1, int* r2, int n0, int n1, int n2) {
    __shared__ int part[1024];
    const int* deg = (blockIdx.x == 0) ? g0 : (blockIdx.x == 1) ? g1 : g2;
    int* rowptr    = (blockIdx.x == 0) ? r0 : (blockIdx.x == 1) ? r1 : r2;
    int N          = (blockIdx.x == 0) ? n0 : (blockIdx.x == 1) ? n1 : n2;
    int tid = threadIdx.x;
    int chunk = (N + 1023) >> 10;
    int start = tid * chunk;
    int end = min(start + chunk, N);
    int s = 0;
    for (int i = start; i < end; i++) s += deg[i];
    part[tid] = s;
    __syncthreads();
    for (int d = 1; d < 1024; d <<= 1) {
        int v = (tid >= d) ? part[tid - d] : 0;
        __syncthreads();
        part[tid] += v;
        __syncthreads();
    }
    int off = part[tid] - s;
    for (int i = start; i < end; i++) { rowptr[i] = off; off += deg[i]; }
    if (tid == 1023) rowptr[N] = part[1023];
}
__global__ void copy3_kernel(const int* a0, const int* a1, const int* a2,
                             int* b0, int* b1, int* b2, int n0, int n1, int n2) {
    int i = blockIdx.x * blockDim.x + threadIdx.x;
    if (i < n0) b0[i] = a0[i];
    else if (i < n0 + n1) b1[i - n0] = a1[i - n0];
    else if (i < n0 + n1 + n2) b2[i - n0 - n1] = a2[i - n0 - n1];
}
__global__ void fill3_kernel(const int* d0, const int* d1, const int* d2,
                             int* c0, int* c1, int* c2,
                             int* p0, int* p1, int* p2) {
    int i = blockIdx.x * blockDim.x + threadIdx.x;
    if (i < E_EDGE) { int pos = atomicAdd(&c0[d0[i]], 1); p0[pos] = i; }
    else if (i < 2 * E_EDGE) { int e = i - E_EDGE; int pos = atomicAdd(&c1[d1[e]], 1); p1[pos] = e; }
    else if (i < 3 * E_EDGE) { int e = i - 2 * E_EDGE; int pos = atomicAdd(&c2[d2[e]], 1); p2[pos] = e; }
}

// ---------------- embedding mean-pool + relu ----------------
__global__ void pool_kernel(const int* __restrict__ tok, const float* __restrict__ emb,
                            float* __restrict__ out, int N) {
    int n = blockIdx.x;
    int c = threadIdx.x;
    __shared__ int ts[T_TOK];
    if (c < T_TOK) ts[c] = tok[n * T_TOK + c];
    __syncthreads();
    float s = 0.0f;
#pragma unroll
    for (int t = 0; t < T_TOK; t++)
        s += emb[(size_t)ts[t] * C_DIM + c];
    s *= (1.0f / (float)T_TOK);
    out[(size_t)n * C_DIM + c] = fmaxf(s, 0.0f);
}

// ---------------- weight prep: W[k][n] fp32 -> Wt_hi/Wt_lo[n][k] bf16 ----------------
__global__ void prep_w(const float* __restrict__ lin_w, const float* __restrict__ kw,
                       const float* __restrict__ qw, const float* __restrict__ vw,
                       const float* __restrict__ aw,
                       __nv_bfloat16* __restrict__ whi, __nv_bfloat16* __restrict__ wlo) {
    extern __shared__ float st[];   // [128][132]
    int w = blockIdx.x;
    const float* src;
    if (w < 2) {
        src = lin_w + (size_t)w * WT_HALVES;
    } else {
        int grp = (w - 2) >> 2, sub = (w - 2) & 3;
        const float* b = (grp == 0) ? kw : (grp == 1) ? qw : (grp == 2) ? vw : aw;
        src = b + (size_t)sub * WT_HALVES;
    }
    int tid = threadIdx.x;
#pragma unroll
    for (int v = 0; v < 16; v++) {
        int i = tid + v * 256;
        int k = i >> 5, n4 = (i & 31) << 2;
        float4 f = *(const float4*)&src[(size_t)k * C_DIM + n4];
        *(float4*)&st[k * 132 + n4] = f;
    }
    __syncthreads();
    __nv_bfloat16* oh = whi + (size_t)w * WT_HALVES;
    __nv_bfloat16* ol = wlo + (size_t)w * WT_HALVES;
#pragma unroll
    for (int v = 0; v < 8; v++) {
        int u = tid + v * 256;
        int n = u & 127, kc = u >> 7;
        uint16_t hb[8], lb[8];
#pragma unroll
        for (int j = 0; j < 8; j++) {
            float f = st[(kc * 8 + j) * 132 + n];
            __nv_bfloat16 h = __float2bfloat16(f);
            __nv_bfloat16 l = __float2bfloat16(f - __bfloat162float(h));
            hb[j] = __bfloat16_as_ushort(h);
            lb[j] = __bfloat16_as_ushort(l);
        }
        *(uint4*)&oh[n * C_DIM + kc * 8] = *(uint4*)hb;
        *(uint4*)&ol[n * C_DIM + kc * 8] = *(uint4*)lb;
    }
}

// ---------------- activation split: X fp32 -> (hi, lo) bf16, optional gelu ----------------
template<int GELU>
__global__ void xsplit(const float* __restrict__ X, __nv_bfloat16* __restrict__ hi,
                       __nv_bfloat16* __restrict__ lo, int n8) {
    int i = blockIdx.x * blockDim.x + threadIdx.x;
    if (i >= n8) return;
    float f[8];
    *(float4*)&f[0] = *(const float4*)&X[(size_t)i * 8];
    *(float4*)&f[4] = *(const float4*)&X[(size_t)i * 8 + 4];
    if (GELU) {
#pragma unroll
        for (int j = 0; j < 8; j++) f[j] = gelu_tanh(f[j]);
    }
    uint16_t hb[8], lb[8];
#pragma unroll
    for (int j = 0; j < 8; j++) {
        __nv_bfloat16 h = __float2bfloat16(f[j]);
        __nv_bfloat16 l = __float2bfloat16(f[j] - __bfloat162float(h));
        hb[j] = __bfloat16_as_ushort(h);
        lb[j] = __bfloat16_as_ushort(l);
    }
    *(uint4*)&hi[(size_t)i * 8] = *(uint4*)hb;
    *(uint4*)&lo[(size_t)i * 8] = *(uint4*)lb;
}

// ---------------- mma.sync GEMM: Y[N,128] = epi( Asplit @ W + b ) ----------------
// A pre-split bf16 (hi/lo), W cached bf16 [n][k] (hi/lo). grid.y selects weight/bias/output
// (fused KQV). 8 warps: 4m x 2n, warp tile 32x64. Inner loop: ldmatrix + HMMA only.
// EPI: 0=none, 1=relu, 2=skip-blend.
#define SMEM_MMA (4 * 128 * BROW * 2)
template<int EPI>
__global__ void __launch_bounds__(256, 1)
mma_gemm2(const __nv_bfloat16* __restrict__ Ahi, const __nv_bfloat16* __restrict__ Alo,
          const __nv_bfloat16* __restrict__ Whi, const __nv_bfloat16* __restrict__ Wlo,
          size_t wstep,
          const float* __restrict__ bias0, const float* __restrict__ bias1,
          const float* __restrict__ bias2,
          float* __restrict__ Y, size_t ystride,
          const float* __restrict__ Xold, const float* __restrict__ skipp, int N) {
    extern __shared__ char smraw[];
    __nv_bfloat16* Ah = (__nv_bfloat16*)smraw;
    __nv_bfloat16* Al = Ah + 128 * BROW;
    __nv_bfloat16* Bh = Al + 128 * BROW;
    __nv_bfloat16* Bl = Bh + 128 * BROW;

    int tid = threadIdx.x, wid = tid >> 5, lane = tid & 31;
    int y = blockIdx.y;
    const __nv_bfloat16* wh = Whi + (size_t)y * wstep;
    const __nv_bfloat16* wl = Wlo + (size_t)y * wstep;
    const float* bias = (y == 0) ? bias0 : ((y == 1) ? bias1 : bias2);
    float* Yo = Y + (size_t)y * ystride;
    int row0 = blockIdx.x * 128;

    // ---- stage all four tiles ----
#pragma unroll
    for (int v = 0; v < 8; v++) {
        int idx = tid + v * 256;        // 0..2047
        int r = idx >> 4, c8 = (idx & 15) * 8;
        *(uint4*)&Bh[r * BROW + c8] = *(const uint4*)&wh[r * C_DIM + c8];
        *(uint4*)&Bl[r * BROW + c8] = *(const uint4*)&wl[r * C_DIM + c8];
        int gr = row0 + r;
        uint4 vh = make_uint4(0, 0, 0, 0), vl = vh;
        if (gr < N) {
            vh = *(const uint4*)&Ahi[(size_t)gr * C_DIM + c8];
            vl = *(const uint4*)&Alo[(size_t)gr * C_DIM + c8];
        }
        *(uint4*)&Ah[r * BROW + c8] = vh;
        *(uint4*)&Al[r * BROW + c8] = vl;
    }
    __syncthreads();

    int wm = wid & 3, wn = wid >> 2;
    int m0 = wm * 32, n0 = wn * 64;

    uint32_t smAh = smem_u32(Ah), smAl = smem_u32(Al);
    uint32_t smBh = smem_u32(Bh), smBl = smem_u32(Bl);

    int grp = lane >> 3, lr = lane & 7;
    // A address pattern: reg grp -> row += (grp&1)*8, k += (grp&2)*4
    int a_r = ((grp & 1) << 3) + lr;
    int a_k = (grp & 2) << 2;              // 0 or 8
    // B address pattern: reg grp -> n-row += (grp&2)*4, k += (grp&1)*8
    int b_r = ((grp & 2) << 2) + lr;
    int b_k = (grp & 1) << 3;

    float acc[16][4];
#pragma unroll
    for (int f = 0; f < 16; f++)
#pragma unroll
        for (int j = 0; j < 4; j++) acc[f][j] = 0.0f;

#pragma unroll
    for (int ks = 0; ks < 8; ks++) {
        int kb = ks * 16;
        uint32_t ahi[2][4], alo[2][4];
#pragma unroll
        for (int mi = 0; mi < 2; mi++) {
            uint32_t ar = (uint32_t)((m0 + mi * 16 + a_r) * BROW + kb + a_k) * 2u;
            LDM4(ahi[mi][0], ahi[mi][1], ahi[mi][2], ahi[mi][3], smAh + ar);
            LDM4(alo[mi][0], alo[mi][1], alo[mi][2], alo[mi][3], smAl + ar);
        }
        uint32_t bh[4][4], bl[4][4];
#pragma unroll
        for (int nb = 0; nb < 4; nb++) {
            uint32_t br = (uint32_t)((n0 + nb * 16 + b_r) * BROW + kb + b_k) * 2u;
            LDM4(bh[nb][0], bh[nb][1], bh[nb][2], bh[nb][3], smBh + br);
            LDM4(bl[nb][0], bl[nb][1], bl[nb][2], bl[nb][3], smBl + br);
        }
#pragma unroll
        for (int ni = 0; ni < 8; ni++) {
            int q = ni >> 1, odd = (ni & 1) << 1;
            uint32_t h0 = bh[q][odd], h1 = bh[q][odd + 1];
            uint32_t l0 = bl[q][odd], l1 = bl[q][odd + 1];
#pragma unroll
            for (int mi = 0; mi < 2; mi++) {
                mma16816(acc[mi * 8 + ni], ahi[mi], h0, h1);
                mma16816(acc[mi * 8 + ni], ahi[mi], l0, l1);
                mma16816(acc[mi * 8 + ni], alo[mi], h0, h1);
            }
        }
    }

    // ---- epilogue (c-frag: rows g,g+8; cols tq*2,+1) ----
    int g = lane >> 2, tq = lane & 3;
    float gg = 0.0f, og = 0.0f;
    if (EPI == 2) {
        gg = 1.0f / (1.0f + expf(-skipp[0]));
        og = 1.0f - gg;
    }
#pragma unroll
    for (int mi = 0; mi < 2; mi++) {
#pragma unroll
        for (int half = 0; half < 2; half++) {
            int r = row0 + m0 + mi * 16 + g + half * 8;
            if (r >= N) continue;
#pragma unroll
            for (int ni = 0; ni < 8; ni++) {
                int c = n0 + ni * 8 + tq * 2;
                float o0 = acc[mi * 8 + ni][half * 2 + 0] + bias[c];
                float o1 = acc[mi * 8 + ni][half * 2 + 1] + bias[c + 1];
                if (EPI == 1) { o0 = fmaxf(o0, 0.0f); o1 = fmaxf(o1, 0.0f); }
                if (EPI == 2) {
                    float2 xo = *(const float2*)&Xold[(size_t)r * C_DIM + c];
                    o0 = gg * o0 + og * xo.x;
                    o1 = gg * o1 + og * xo.y;
                }
                *(float2*)&Yo[(size_t)r * C_DIM + c] = make_float2(o0, o1);
            }
        }
    }
}

// ---------------- fused per-head relation transforms ----------------
__global__ void rel2_kernel(const float* __restrict__ K, const float* __restrict__ V,
                            const float* __restrict__ A, const float* __restrict__ M,
                            float* __restrict__ KR, float* __restrict__ VR, int N) {
    __shared__ float As[H_HEAD * D_HEAD * D_HEAD];
    __shared__ float Ms[H_HEAD * D_HEAD * D_HEAD];
    __shared__ float kin[4][C_DIM];
    __shared__ float vin[4][C_DIM];
    int tid = threadIdx.y * C_DIM + threadIdx.x;
    for (int i = tid; i < H_HEAD * D_HEAD * D_HEAD; i += 512) {
        As[i] = A[i];
        Ms[i] = M[i];
    }
    int n = blockIdx.x * 4 + threadIdx.y;
    int c = threadIdx.x;
    int h = c >> 4, e = c & 15;
    if (n < N) {
        kin[threadIdx.y][c] = K[(size_t)n * C_DIM + c];
        vin[threadIdx.y][c] = V[(size_t)n * C_DIM + c];
    }
    __syncthreads();
    if (n < N) {
        float sk = 0.0f, sv = 0.0f;
#pragma unroll
        for (int d = 0; d < D_HEAD; d++) {
            float a = As[(h * 16 + d) * 16 + e];
            float m = Ms[(h * 16 + d) * 16 + e];
            sk = fmaf(kin[threadIdx.y][h * 16 + d], a, sk);
            sv = fmaf(vin[threadIdx.y][h * 16 + d], m, sv);
        }
        KR[(size_t)n * C_DIM + c] = sk;
        VR[(size_t)n * C_DIM + c] = sv;
    }
}

// ---------------- CSR gather: one-pass online softmax + aggregation ----------------
__global__ void gather_kernel(const int* __restrict__ rowptr, const int* __restrict__ perm,
                              const int* __restrict__ srcarr,
                              const float* __restrict__ Q, const float* __restrict__ KR,
                              const float* __restrict__ VR, const float* __restrict__ prel,
                              float* __restrict__ agg, int Ndst) {
    int idx = blockIdx.x * blockDim.x + threadIdx.x;
    if (idx >= Ndst * H_HEAD) return;
    int d = idx >> 3, h = idx & 7;
    int beg = rowptr[d], end = rowptr[d + 1];
    if (beg == end) return;
    float pscale = prel[h] * 0.25f;
    const float4* qp = (const float4*)&Q[(size_t)d * C_DIM + h * 16];
    float4 q0 = qp[0], q1 = qp[1], q2 = qp[2], q3 = qp[3];
    float m = -INFINITY, s = 0.0f;
    float acc[16];
#pragma unroll
    for (int i = 0; i < 16; i++) acc[i] = 0.0f;
    for (int j = beg; j < end; j++) {
        int sn = srcarr[perm[j]];
        const float4* kp = (const float4*)&KR[(size_t)sn * C_DIM + h * 16];
        float4 k0 = kp[0], k1 = kp[1], k2 = kp[2], k3 = kp[3];
        float l = q0.x * k0.x + q0.y * k0.y + q0.z * k0.z + q0.w * k0.w
                + q1.x * k1.x + q1.y * k1.y + q1.z * k1.z + q1.w * k1.w
                + q2.x * k2.x + q2.y * k2.y + q2.z * k2.z + q2.w * k2.w
                + q3.x * k3.x + q3.y * k3.y + q3.z * k3.z + q3.w * k3.w;
        l *= pscale;
        float mn = fmaxf(m, l);
        float sc = expf(m - mn);
        float w  = expf(l - mn);
        s = s * sc + w;
        m = mn;
        const float4* vp = (const float4*)&VR[(size_t)sn * C_DIM + h * 16];
#pragma unroll
        for (int i = 0; i < 4; i++) {
            float4 v = vp[i];
            acc[4 * i + 0] = acc[4 * i + 0] * sc + w * v.x;
            acc[4 * i + 1] = acc[4 * i + 1] * sc + w * v.y;
            acc[4 * i + 2] = acc[4 * i + 2] * sc + w * v.z;
            acc[4 * i + 3] = acc[4 * i + 3] * sc + w * v.w;
        }
    }
    float inv = 1.0f / (s + 1e-16f);
    float4* ap = (float4*)&agg[(size_t)d * C_DIM + h * 16];
#pragma unroll
    for (int i = 0; i < 4; i++) {
        float4 a = ap[i];
        a.x += acc[4 * i + 0] * inv;
        a.y += acc[4 * i + 1] * inv;
        a.z += acc[4 * i + 2] * inv;
        a.w += acc[4 * i + 3] * inv;
        ap[i] = a;
    }
}

// ---------------- host orchestration ----------------
static inline int cdiv(int a, int b) { return (a + b - 1) / b; }

#define SMEM_PREP (128 * 132 * 4)

extern "C" void kernel_launch(void* const* d_in, const int* in_sizes, int n_in,
                              void* d_out, int out_size) {
    (void)in_sizes; (void)n_in; (void)out_size;
    const int*   tok_s = (const int*)d_in[0];
    const int*   tok_f = (const int*)d_in[1];
    const int*   esrc[3] = {(const int*)d_in[2], (const int*)d_in[4], (const int*)d_in[6]};
    const int*   edst[3] = {(const int*)d_in[3], (const int*)d_in[5], (const int*)d_in[7]};
    const float* emb   = (const float*)d_in[8];
    const float* lin_w = (const float*)d_in[9];
    const float* lin_b = (const float*)d_in[10];
    const float* kw = (const float*)d_in[11], *kbi = (const float*)d_in[12];
    const float* qw = (const float*)d_in[13], *qbi = (const float*)d_in[14];
    const float* vw = (const float*)d_in[15], *vbi = (const float*)d_in[16];
    const float* aw = (const float*)d_in[17], *abi = (const float*)d_in[18];
    const float* skip  = (const float*)d_in[19];
    const float* a_rel = (const float*)d_in[20];
    const float* m_rel = (const float*)d_in[21];
    const float* p_rel = (const float*)d_in[22];
    float* out = (float*)d_out;

    float* S = nullptr;
    cudaGetSymbolAddress((void**)&S, g_scratch);

    cudaFuncSetAttribute(prep_w, cudaFuncAttributeMaxDynamicSharedMemorySize, SMEM_PREP);
    cudaFuncSetAttribute(mma_gemm2<0>, cudaFuncAttributeMaxDynamicSharedMemorySize, SMEM_MMA);
    cudaFuncSetAttribute(mma_gemm2<1>, cudaFuncAttributeMaxDynamicSharedMemorySize, SMEM_MMA);
    cudaFuncSetAttribute(mma_gemm2<2>, cudaFuncAttributeMaxDynamicSharedMemorySize, SMEM_MMA);

    float* x[2]    = {S + OFF_X0,  S + OFF_X1};
    float* xn[2]   = {S + OFF_XN0, S + OFF_XN1};
    float* bufK[2] = {S + OFF_K0,  S + OFF_K1};
    float* bufQ[2] = {S + OFF_Q0,  S + OFF_Q1};
    float* bufV[2] = {S + OFF_V0,  S + OFF_V1};
    float* kr   = S + OFF_KR;
    float* vr   = S + OFF_VR;
    float* agg[2] = {S + OFF_AGG0, S + OFF_AGG1};
    __nv_bfloat16* whi = (__nv_bfloat16*)(S + OFF_WT);
    __nv_bfloat16* wlo = whi + (size_t)N_WMAT * WT_HALVES;
    __nv_bfloat16* xhi = (__nv_bfloat16*)(S + OFF_XSP);
    __nv_bfloat16* xlo = xhi + SZ_S;

    const int NN[2] = {N_STMT, N_FUNC};
    const size_t SZT[2] = {SZ_S, SZ_F};
    const int ST[3] = {0, 0, 1};
    const int DT[3] = {0, 1, 0};

    auto WHI = [&](int w) { return whi + (size_t)w * WT_HALVES; };
    auto WLO = [&](int w) { return wlo + (size_t)w * WT_HALVES; };

    // ---- weight cache ----
    prep_w<<<N_WMAT, 256, SMEM_PREP>>>(lin_w, kw, qw, vw, aw, whi, wlo);

    // ---- CSR region ----
    int* csr = (int*)(S + OFF_CSR);
    const int ndst_r[3] = {N_STMT, N_FUNC, N_STMT};
    int* rp[3]; int* pm[3]; int* cu[3];
    {
        size_t off = 0;
        for (int r = 0; r < 3; r++) {
            rp[r] = csr + off; off += (size_t)ndst_r[r] + 1;
            pm[r] = csr + off; off += E_EDGE;
            cu[r] = csr + off; off += ndst_r[r];
        }
    }
    int ndsum = ndst_r[0] + ndst_r[1] + ndst_r[2];
    zero3_kernel<<<cdiv(ndsum, 256), 256>>>(cu[0], cu[1], cu[2], ndst_r[0], ndst_r[1], ndst_r[2]);
    count3_kernel<<<cdiv(3 * E_EDGE, 256), 256>>>(edst[0], edst[1], edst[2], cu[0], cu[1], cu[2]);
    scan3_kernel<<<3, 1024>>>(cu[0], cu[1], cu[2], rp[0], rp[1], rp[2],
                              ndst_r[0], ndst_r[1], ndst_r[2]);
    copy3_kernel<<<cdiv(ndsum, 256), 256>>>(rp[0], rp[1], rp[2], cu[0], cu[1], cu[2],
                                            ndst_r[0], ndst_r[1], ndst_r[2]);
    fill3_kernel<<<cdiv(3 * E_EDGE, 256), 256>>>(edst[0], edst[1], edst[2],
                                                 cu[0], cu[1], cu[2], pm[0], pm[1], pm[2]);

    // ---- encode ----
    pool_kernel<<<N_STMT, C_DIM>>>(tok_s, emb, agg[0], N_STMT);
    pool_kernel<<<N_FUNC, C_DIM>>>(tok_f, emb, agg[1], N_FUNC);
    for (int t = 0; t < 2; t++) {
        int n8 = NN[t] * 16;
        xsplit<0><<<cdiv(n8, 256), 256>>>(agg[t], xhi, xlo, n8);
        mma_gemm2<1><<<dim3(cdiv(NN[t], 128), 1), 256, SMEM_MMA>>>(
            xhi, xlo, WHI(t), WLO(t), 0,
            lin_b + (size_t)t * C_DIM, nullptr, nullptr,
            x[t], 0, nullptr, nullptr, NN[t]);
    }

    float* cur[2] = {x[0], x[1]};
    float* nxt[2] = {xn[0], xn[1]};

    for (int l = 0; l < L_LAYER; l++) {
        // fused K/Q/V projections (grid.y = 3; outputs K,Q,V contiguous with stride SZT[t])
        for (int t = 0; t < 2; t++) {
            int lt = l * 2 + t;
            size_t bo = (size_t)lt * C_DIM;
            int n8 = NN[t] * 16;
            xsplit<0><<<cdiv(n8, 256), 256>>>(cur[t], xhi, xlo, n8);
            mma_gemm2<0><<<dim3(cdiv(NN[t], 128), 3), 256, SMEM_MMA>>>(
                xhi, xlo, WHI(2 + lt), WLO(2 + lt), (size_t)4 * WT_HALVES,
                kbi + bo, qbi + bo, vbi + bo,
                bufK[t], SZT[t], nullptr, nullptr, NN[t]);
        }
        fill_kernel<<<cdiv((int)(SZ_S + SZ_F), 256), 256>>>(agg[0], 0.0f, (int)(SZ_S + SZ_F));

        for (int r = 0; r < 3; r++) {
            int st = ST[r], dt = DT[r];
            size_t ro = (size_t)(l * 3 + r) * H_HEAD * D_HEAD * D_HEAD;
            dim3 rb(C_DIM, 4);
            rel2_kernel<<<cdiv(NN[st], 4), rb>>>(bufK[st], bufV[st], a_rel + ro, m_rel + ro,
                                                 kr, vr, NN[st]);
            const float* pr = p_rel + (size_t)(l * 3 + r) * H_HEAD;
            gather_kernel<<<cdiv(NN[dt] * H_HEAD, 256), 256>>>(
                rp[r], pm[r], esrc[r], bufQ[dt], kr, vr, pr, agg[dt], NN[dt]);
        }

        // a-projection: gelu folded into the split, then skip-blend epilogue
        for (int t = 0; t < 2; t++) {
            int lt = l * 2 + t;
            size_t bo = (size_t)lt * C_DIM;
            float* yo = (l == L_LAYER - 1)
                        ? out + (t == 1 ? (size_t)N_STMT * C_DIM : 0)
                        : nxt[t];
            int n8 = NN[t] * 16;
            xsplit<1><<<cdiv(n8, 256), 256>>>(agg[t], xhi, xlo, n8);
            mma_gemm2<2><<<dim3(cdiv(NN[t], 128), 1), 256, SMEM_MMA>>>(
                xhi, xlo, WHI(14 + lt), WLO(14 + lt), 0,
                abi + bo, nullptr, nullptr,
                yo, 0, cur[t], skip + lt, NN[t]);
        }
        float* t0 = cur[0]; float* t1 = cur[1];
        cur[0] = nxt[0]; cur[1] = nxt[1];
        nxt[0] = t0; nxt[1] = t1;
    }
}